// round 1
// baseline (speedup 1.0000x reference)
#include <cuda_runtime.h>
#include <cuda_bf16.h>
#include <math.h>

// Problem constants
#define TT   512     // tokens (B*S)
#define HD   2048    // hidden dim
#define EE   32      // experts
#define KTOP 4       // top-k
#define FF   1024    // expert ffn dim
#define NZ   16
#define ZHD  512

// Scratch (static device globals; allocation-free per harness rules)
__device__ float g_zh[TT * ZHD];                    // 1 MB
__device__ float g_act[(size_t)EE * TT * FF];       // 64 MB (expert-slot-major activations)
__device__ int   g_cnt[EE];
__device__ int   g_tok[EE * TT];
__device__ float g_wgt[EE * TT];

// ---------------------------------------------------------------------------
// K0: zero output + expert counters
// ---------------------------------------------------------------------------
__global__ void k_zero(float* __restrict__ out) {
    int i = blockIdx.x * blockDim.x + threadIdx.x;
    if (i < TT * HD) out[i] = 0.0f;
    if (i < EE) g_cnt[i] = 0;
}

// ---------------------------------------------------------------------------
// K1: zh = silu(x @ z_w1^T + b1)   [512 x 512], K=2048
// 64x64 block tile, BK=16, 4x4 micro-tile, 256 threads
// ---------------------------------------------------------------------------
__global__ __launch_bounds__(256) void k_zh(const float* __restrict__ x,
                                            const float* __restrict__ w1,
                                            const float* __restrict__ b1) {
    __shared__ float As[16][64];
    __shared__ float Bs[16][64];
    int m0 = blockIdx.y * 64, n0 = blockIdx.x * 64;
    int tx = threadIdx.x & 15, ty = threadIdx.x >> 4;
    float acc[4][4] = {};
    for (int k0 = 0; k0 < HD; k0 += 16) {
        for (int i = threadIdx.x; i < 64 * 16; i += 256) {
            int r = i >> 4, c = i & 15;
            As[c][r] = x[(m0 + r) * HD + k0 + c];
            Bs[c][r] = w1[(n0 + r) * HD + k0 + c];
        }
        __syncthreads();
#pragma unroll
        for (int k = 0; k < 16; k++) {
            float a[4], b[4];
#pragma unroll
            for (int i = 0; i < 4; i++) a[i] = As[k][ty * 4 + i];
#pragma unroll
            for (int j = 0; j < 4; j++) b[j] = Bs[k][tx * 4 + j];
#pragma unroll
            for (int i = 0; i < 4; i++)
#pragma unroll
                for (int j = 0; j < 4; j++) acc[i][j] += a[i] * b[j];
        }
        __syncthreads();
    }
#pragma unroll
    for (int i = 0; i < 4; i++)
#pragma unroll
        for (int j = 0; j < 4; j++) {
            int m = m0 + ty * 4 + i, n = n0 + tx * 4 + j;
            float v = acc[i][j] + b1[n];
            g_zh[m * ZHD + n] = v / (1.0f + expf(-v));  // silu
        }
}

// ---------------------------------------------------------------------------
// K2: per-token router. 1 block = 1 token, 128 threads.
//  - gate logits (32 dots of 2048)
//  - z logits (16 dots of 512) + gumbel -> argmax -> U-row bias
//  - softmax over 32, top-4, atomic append to expert lists
// ---------------------------------------------------------------------------
__global__ __launch_bounds__(128) void k_router(const float* __restrict__ x,
                                                const float* __restrict__ u,
                                                const float* __restrict__ gate_w,
                                                const float* __restrict__ z_w2,
                                                const float* __restrict__ z_b2,
                                                const float* __restrict__ Umat) {
    int t = blockIdx.x;
    __shared__ float xs[HD];
    __shared__ float rl[EE];
    __shared__ float zl[NZ];
    int tid = threadIdx.x, lane = tid & 31, warp = tid >> 5;

    for (int i = tid; i < HD; i += 128) xs[i] = x[t * HD + i];
    __syncthreads();

    for (int e = warp; e < EE; e += 4) {
        float s = 0.0f;
        const float* gw = gate_w + e * HD;
        for (int i = lane; i < HD; i += 32) s += xs[i] * gw[i];
#pragma unroll
        for (int o = 16; o; o >>= 1) s += __shfl_down_sync(0xffffffffu, s, o);
        if (lane == 0) rl[e] = s;
    }
    for (int j = warp; j < NZ; j += 4) {
        float s = 0.0f;
        const float* zw = z_w2 + j * ZHD;
        const float* zh = g_zh + t * ZHD;
        for (int i = lane; i < ZHD; i += 32) s += zh[i] * zw[i];
#pragma unroll
        for (int o = 16; o; o >>= 1) s += __shfl_down_sync(0xffffffffu, s, o);
        if (lane == 0) zl[j] = s + z_b2[j];
    }
    __syncthreads();

    if (tid == 0) {
        // gumbel-perturbed argmax (softmax monotone, TAU=1)
        int zi = 0;
        float best = -1e30f;
        for (int j = 0; j < NZ; j++) {
            float g = -logf(-logf(u[t * NZ + j]));
            float v = zl[j] + g;
            if (v > best) { best = v; zi = j; }
        }
        float lg[EE];
        float mx = -1e30f;
        for (int e = 0; e < EE; e++) {
            lg[e] = rl[e] + Umat[zi * EE + e];
            mx = fmaxf(mx, lg[e]);
        }
        float sum = 0.0f;
        for (int e = 0; e < EE; e++) { lg[e] = expf(lg[e] - mx); sum += lg[e]; }
        float inv = 1.0f / sum;
        // top-4 (first-max on ties == jax lower-index tiebreak)
        for (int k = 0; k < KTOP; k++) {
            int be = 0;
            float bv = -1.0f;
            for (int e = 0; e < EE; e++)
                if (lg[e] > bv) { bv = lg[e]; be = e; }
            float w = bv * inv;
            lg[be] = -1.0f;
            int pos = atomicAdd(&g_cnt[be], 1);
            g_tok[be * TT + pos] = t;
            g_wgt[be * TT + pos] = w;
        }
    }
}

// ---------------------------------------------------------------------------
// K3: per-expert gate/up GEMMs + SwiGLU * comb -> g_act
// grid (F/64, E). 64-token x 64-F tiles, BK=16, dual 4x4 micro-tiles.
// ---------------------------------------------------------------------------
__global__ __launch_bounds__(256) void k_gateup(const float* __restrict__ x,
                                                const float* __restrict__ Wg,
                                                const float* __restrict__ Wu) {
    int e = blockIdx.y;
    int n = g_cnt[e];
    if (n == 0) return;
    int f0 = blockIdx.x * 64;
    __shared__ float As[16][64];
    __shared__ float Bg[16][64];
    __shared__ float Bu[16][64];
    __shared__ int toks[64];
    int tx = threadIdx.x & 15, ty = threadIdx.x >> 4;
    const float* wg = Wg + (size_t)e * HD * FF;
    const float* wu = Wu + (size_t)e * HD * FF;

    for (int s0 = 0; s0 < n; s0 += 64) {
        int nt = min(64, n - s0);
        if (threadIdx.x < 64)
            toks[threadIdx.x] = (threadIdx.x < nt) ? g_tok[e * TT + s0 + threadIdx.x] : 0;
        __syncthreads();

        float ag[4][4] = {}, au[4][4] = {};
        for (int k0 = 0; k0 < HD; k0 += 16) {
            for (int i = threadIdx.x; i < 64 * 16; i += 256) {
                int r = i >> 4, c = i & 15;
                As[c][r] = (r < nt) ? x[toks[r] * HD + k0 + c] : 0.0f;
            }
            for (int i = threadIdx.x; i < 16 * 64; i += 256) {
                int kk = i >> 6, f = i & 63;
                Bg[kk][f] = wg[(size_t)(k0 + kk) * FF + f0 + f];
                Bu[kk][f] = wu[(size_t)(k0 + kk) * FF + f0 + f];
            }
            __syncthreads();
#pragma unroll
            for (int k = 0; k < 16; k++) {
                float a[4], bg[4], bu[4];
#pragma unroll
                for (int i = 0; i < 4; i++) a[i] = As[k][ty * 4 + i];
#pragma unroll
                for (int j = 0; j < 4; j++) { bg[j] = Bg[k][tx * 4 + j]; bu[j] = Bu[k][tx * 4 + j]; }
#pragma unroll
                for (int i = 0; i < 4; i++)
#pragma unroll
                    for (int j = 0; j < 4; j++) {
                        ag[i][j] += a[i] * bg[j];
                        au[i][j] += a[i] * bu[j];
                    }
            }
            __syncthreads();
        }
#pragma unroll
        for (int i = 0; i < 4; i++) {
            int r = ty * 4 + i;
            if (r < nt) {
                float wc = g_wgt[e * TT + s0 + r];
#pragma unroll
                for (int j = 0; j < 4; j++) {
                    float gp = ag[i][j];
                    float act = gp / (1.0f + expf(-gp)) * au[i][j] * wc;
                    g_act[((size_t)e * TT + s0 + r) * FF + f0 + tx * 4 + j] = act;
                }
            }
        }
        __syncthreads();
    }
}

// ---------------------------------------------------------------------------
// K4: per-expert down projection, atomicAdd into out.
// grid (H/64, E). 64-token x 64-H tiles over F=1024.
// ---------------------------------------------------------------------------
__global__ __launch_bounds__(256) void k_down(const float* __restrict__ Wd,
                                              float* __restrict__ out) {
    int e = blockIdx.y;
    int n = g_cnt[e];
    if (n == 0) return;
    int h0 = blockIdx.x * 64;
    __shared__ float As[16][64];
    __shared__ float Bs[16][64];
    int tx = threadIdx.x & 15, ty = threadIdx.x >> 4;
    const float* wd = Wd + (size_t)e * FF * HD;

    for (int s0 = 0; s0 < n; s0 += 64) {
        int nt = min(64, n - s0);
        float acc[4][4] = {};
        for (int k0 = 0; k0 < FF; k0 += 16) {
            for (int i = threadIdx.x; i < 64 * 16; i += 256) {
                int r = i >> 4, c = i & 15;
                As[c][r] = (r < nt) ? g_act[((size_t)e * TT + s0 + r) * FF + k0 + c] : 0.0f;
            }
            for (int i = threadIdx.x; i < 16 * 64; i += 256) {
                int kk = i >> 6, h = i & 63;
                Bs[kk][h] = wd[(size_t)(k0 + kk) * HD + h0 + h];
            }
            __syncthreads();
#pragma unroll
            for (int k = 0; k < 16; k++) {
                float a[4], b[4];
#pragma unroll
                for (int i = 0; i < 4; i++) a[i] = As[k][ty * 4 + i];
#pragma unroll
                for (int j = 0; j < 4; j++) b[j] = Bs[k][tx * 4 + j];
#pragma unroll
                for (int i = 0; i < 4; i++)
#pragma unroll
                    for (int j = 0; j < 4; j++) acc[i][j] += a[i] * b[j];
            }
            __syncthreads();
        }
#pragma unroll
        for (int i = 0; i < 4; i++) {
            int r = ty * 4 + i;
            if (r < nt) {
                int t = g_tok[e * TT + s0 + r];
#pragma unroll
                for (int j = 0; j < 4; j++)
                    atomicAdd(&out[t * HD + h0 + tx * 4 + j], acc[i][j]);
            }
        }
    }
}

// ---------------------------------------------------------------------------
// launch
// ---------------------------------------------------------------------------
extern "C" void kernel_launch(void* const* d_in, const int* in_sizes, int n_in,
                              void* d_out, int out_size) {
    const float* x      = (const float*)d_in[0];   // [512, 2048]
    const float* u      = (const float*)d_in[1];   // [512, 16]
    const float* gate_w = (const float*)d_in[2];   // [32, 2048]
    const float* z_w1   = (const float*)d_in[3];   // [512, 2048]
    const float* z_b1   = (const float*)d_in[4];   // [512]
    const float* z_w2   = (const float*)d_in[5];   // [16, 512]
    const float* z_b2   = (const float*)d_in[6];   // [16]
    const float* Umat   = (const float*)d_in[7];   // [16, 32]
    const float* Wg     = (const float*)d_in[8];   // [32, 2048, 1024]
    const float* Wu     = (const float*)d_in[9];   // [32, 2048, 1024]
    const float* Wd     = (const float*)d_in[10];  // [32, 1024, 2048]
    float* out = (float*)d_out;                    // [512, 2048]

    k_zero<<<(TT * HD + 255) / 256, 256>>>(out);
    k_zh<<<dim3(ZHD / 64, TT / 64), 256>>>(x, z_w1, z_b1);
    k_router<<<TT, 128>>>(x, u, gate_w, z_w2, z_b2, Umat);
    k_gateup<<<dim3(FF / 64, EE), 256>>>(x, Wg, Wu);
    k_down<<<dim3(HD / 64, EE), 256>>>(Wd, out);
}

// round 2
// speedup vs baseline: 2.7011x; 2.7011x over previous
#include <cuda_runtime.h>
#include <math.h>

#define TT   512
#define HD   2048
#define EE   32
#define KTOP 4
#define FF   1024
#define NZ   16
#define ZHD  512

__device__ float g_zh[TT * ZHD];
__device__ float g_act[(size_t)EE * TT * FF];
__device__ int   g_cnt[EE];
__device__ int   g_tok[EE * TT];
__device__ float g_wgt[EE * TT];

__device__ __forceinline__ unsigned f2tf(float f) {
    unsigned u;
    asm("cvt.rna.tf32.f32 %0, %1;" : "=r"(u) : "f"(f));
    return u;
}

__device__ __forceinline__ void mma_tf32(float& d0, float& d1, float& d2, float& d3,
                                         unsigned a0, unsigned a1, unsigned a2, unsigned a3,
                                         unsigned b0, unsigned b1) {
    asm volatile("mma.sync.aligned.m16n8k8.row.col.f32.tf32.tf32.f32 "
                 "{%0,%1,%2,%3}, {%4,%5,%6,%7}, {%8,%9}, {%0,%1,%2,%3};"
                 : "+f"(d0), "+f"(d1), "+f"(d2), "+f"(d3)
                 : "r"(a0), "r"(a1), "r"(a2), "r"(a3), "r"(b0), "r"(b1));
}

// ---------------------------------------------------------------------------
// K0: zero output + expert counters
// ---------------------------------------------------------------------------
__global__ void k_zero(float* __restrict__ out) {
    int i = blockIdx.x * blockDim.x + threadIdx.x;
    if (i < TT * HD) out[i] = 0.0f;
    if (i < EE) g_cnt[i] = 0;
}

// ---------------------------------------------------------------------------
// K1: zh = silu(x @ z_w1^T + b1). M=128 tokens, N=64, K=HD. tf32 mma.
// grid (ZHD/64, TT/128)
// ---------------------------------------------------------------------------
__global__ __launch_bounds__(256, 2) void k_zh(const float* __restrict__ x,
                                               const float* __restrict__ w1,
                                               const float* __restrict__ b1) {
    int m0 = blockIdx.y * 128, n0 = blockIdx.x * 64;
    __shared__ unsigned As[128][20];
    __shared__ unsigned Bs[64][20];
    int tid = threadIdx.x, lane = tid & 31, warp = tid >> 5;
    int wm = warp >> 1, wn = warp & 1;
    int lq = lane >> 2, lr = lane & 3;
    int bn = tid >> 2;            // 0..63  (n row for B staging)
    int bkc = (tid & 3) * 4;      // k offset for B staging

    float acc[2][4][4] = {};
    float4 rA[2], rB;

    // prologue: k0 = 0
    {
#pragma unroll
        for (int p = 0; p < 2; p++) {
            int s = tid + p * 256, r = s >> 2, kc = (s & 3) * 4;
            rA[p] = *(const float4*)&x[(size_t)(m0 + r) * HD + kc];
        }
        rB = *(const float4*)&w1[(size_t)(n0 + bn) * HD + bkc];
    }
#pragma unroll
    for (int p = 0; p < 2; p++) {
        int s = tid + p * 256, r = s >> 2, kc = (s & 3) * 4;
        uint4 w = {f2tf(rA[p].x), f2tf(rA[p].y), f2tf(rA[p].z), f2tf(rA[p].w)};
        *(uint4*)&As[r][kc] = w;
    }
    {
        uint4 w = {f2tf(rB.x), f2tf(rB.y), f2tf(rB.z), f2tf(rB.w)};
        *(uint4*)&Bs[bn][bkc] = w;
    }
    __syncthreads();

    for (int k0 = 0; k0 < HD; k0 += 16) {
        bool more = (k0 + 16) < HD;
        if (more) {
            int kn = k0 + 16;
#pragma unroll
            for (int p = 0; p < 2; p++) {
                int s = tid + p * 256, r = s >> 2, kc = (s & 3) * 4;
                rA[p] = *(const float4*)&x[(size_t)(m0 + r) * HD + kn + kc];
            }
            rB = *(const float4*)&w1[(size_t)(n0 + bn) * HD + kn + bkc];
        }
#pragma unroll
        for (int k8 = 0; k8 < 2; k8++) {
            int kb = k8 * 8 + lr;
            unsigned a[2][4];
#pragma unroll
            for (int mi = 0; mi < 2; mi++) {
                int r = wm * 32 + mi * 16 + lq;
                a[mi][0] = As[r][kb];     a[mi][1] = As[r + 8][kb];
                a[mi][2] = As[r][kb + 4]; a[mi][3] = As[r + 8][kb + 4];
            }
#pragma unroll
            for (int ni = 0; ni < 4; ni++) {
                int nn = wn * 32 + ni * 8 + lq;
                unsigned b0 = Bs[nn][kb], b1r = Bs[nn][kb + 4];
#pragma unroll
                for (int mi = 0; mi < 2; mi++)
                    mma_tf32(acc[mi][ni][0], acc[mi][ni][1], acc[mi][ni][2], acc[mi][ni][3],
                             a[mi][0], a[mi][1], a[mi][2], a[mi][3], b0, b1r);
            }
        }
        __syncthreads();
        if (more) {
#pragma unroll
            for (int p = 0; p < 2; p++) {
                int s = tid + p * 256, r = s >> 2, kc = (s & 3) * 4;
                uint4 w = {f2tf(rA[p].x), f2tf(rA[p].y), f2tf(rA[p].z), f2tf(rA[p].w)};
                *(uint4*)&As[r][kc] = w;
            }
            uint4 w = {f2tf(rB.x), f2tf(rB.y), f2tf(rB.z), f2tf(rB.w)};
            *(uint4*)&Bs[bn][bkc] = w;
            __syncthreads();
        }
    }
#pragma unroll
    for (int mi = 0; mi < 2; mi++)
#pragma unroll
        for (int half = 0; half < 2; half++) {
            int r = m0 + wm * 32 + mi * 16 + lq + half * 8;
#pragma unroll
            for (int ni = 0; ni < 4; ni++)
#pragma unroll
                for (int c = 0; c < 2; c++) {
                    int col = n0 + wn * 32 + ni * 8 + lr * 2 + c;
                    float v = acc[mi][ni][half * 2 + c] + b1[col];
                    g_zh[(size_t)r * ZHD + col] = v / (1.0f + expf(-v));
                }
        }
}

// ---------------------------------------------------------------------------
// K2: per-token router (unchanged from R1; small cost)
// ---------------------------------------------------------------------------
__global__ __launch_bounds__(128) void k_router(const float* __restrict__ x,
                                                const float* __restrict__ u,
                                                const float* __restrict__ gate_w,
                                                const float* __restrict__ z_w2,
                                                const float* __restrict__ z_b2,
                                                const float* __restrict__ Umat) {
    int t = blockIdx.x;
    __shared__ float xs[HD];
    __shared__ float rl[EE];
    __shared__ float zl[NZ];
    int tid = threadIdx.x, lane = tid & 31, warp = tid >> 5;

    for (int i = tid; i < HD; i += 128) xs[i] = x[t * HD + i];
    __syncthreads();

    for (int e = warp; e < EE; e += 4) {
        float s = 0.0f;
        const float* gw = gate_w + e * HD;
        for (int i = lane; i < HD; i += 32) s += xs[i] * gw[i];
#pragma unroll
        for (int o = 16; o; o >>= 1) s += __shfl_down_sync(0xffffffffu, s, o);
        if (lane == 0) rl[e] = s;
    }
    for (int j = warp; j < NZ; j += 4) {
        float s = 0.0f;
        const float* zw = z_w2 + j * ZHD;
        const float* zh = g_zh + t * ZHD;
        for (int i = lane; i < ZHD; i += 32) s += zh[i] * zw[i];
#pragma unroll
        for (int o = 16; o; o >>= 1) s += __shfl_down_sync(0xffffffffu, s, o);
        if (lane == 0) zl[j] = s + z_b2[j];
    }
    __syncthreads();

    if (tid == 0) {
        int zi = 0;
        float best = -1e30f;
        for (int j = 0; j < NZ; j++) {
            float g = -logf(-logf(u[t * NZ + j]));
            float v = zl[j] + g;
            if (v > best) { best = v; zi = j; }
        }
        float lg[EE];
        float mx = -1e30f;
        for (int e = 0; e < EE; e++) {
            lg[e] = rl[e] + Umat[zi * EE + e];
            mx = fmaxf(mx, lg[e]);
        }
        float sum = 0.0f;
        for (int e = 0; e < EE; e++) { lg[e] = expf(lg[e] - mx); sum += lg[e]; }
        float inv = 1.0f / sum;
        for (int k = 0; k < KTOP; k++) {
            int be = 0;
            float bv = -1.0f;
            for (int e = 0; e < EE; e++)
                if (lg[e] > bv) { bv = lg[e]; be = e; }
            float w = bv * inv;
            lg[be] = -1.0f;
            int pos = atomicAdd(&g_cnt[be], 1);
            g_tok[be * TT + pos] = t;
            g_wgt[be * TT + pos] = w;
        }
    }
}

// ---------------------------------------------------------------------------
// K3: gate/up GEMMs + SwiGLU*comb -> g_act. tf32 mma.
// M=128 gathered tokens, N=64 (per Wg and Wu), K=HD. grid (FF/64, EE)
// ---------------------------------------------------------------------------
__global__ __launch_bounds__(256, 2) void k_gateup(const float* __restrict__ x,
                                                   const float* __restrict__ Wg,
                                                   const float* __restrict__ Wu) {
    int e = blockIdx.y;
    int n = g_cnt[e];
    if (n == 0) return;
    int f0 = blockIdx.x * 64;
    __shared__ unsigned As[128][20];
    __shared__ unsigned Bg[64][20];
    __shared__ unsigned Bu[64][20];
    __shared__ int toks[128];
    int tid = threadIdx.x, lane = tid & 31, warp = tid >> 5;
    int wm = warp >> 1, wn = warp & 1;
    int lq = lane >> 2, lr = lane & 3;
    const float* wg = Wg + (size_t)e * HD * FF + f0;
    const float* wu = Wu + (size_t)e * HD * FF + f0;
    int bk = tid & 15;          // k within 16 (B staging)
    int bn = (tid >> 4) * 4;    // n base (B staging)

    for (int s0 = 0; s0 < n; s0 += 128) {
        __syncthreads();
        int nt = min(128, n - s0);
        if (tid < 128) toks[tid] = (tid < nt) ? g_tok[e * TT + s0 + tid] : 0;
        __syncthreads();

        float accg[2][4][4] = {}, accu[2][4][4] = {};
        float4 rA[2], rG, rU;

        // prologue k0=0
#pragma unroll
        for (int p = 0; p < 2; p++) {
            int s = tid + p * 256, r = s >> 2, kc = (s & 3) * 4;
            rA[p] = (r < nt) ? *(const float4*)&x[(size_t)toks[r] * HD + kc]
                             : make_float4(0.f, 0.f, 0.f, 0.f);
        }
        rG = *(const float4*)&wg[(size_t)bk * FF + bn];
        rU = *(const float4*)&wu[(size_t)bk * FF + bn];
#pragma unroll
        for (int p = 0; p < 2; p++) {
            int s = tid + p * 256, r = s >> 2, kc = (s & 3) * 4;
            uint4 w = {f2tf(rA[p].x), f2tf(rA[p].y), f2tf(rA[p].z), f2tf(rA[p].w)};
            *(uint4*)&As[r][kc] = w;
        }
        Bg[bn + 0][bk] = f2tf(rG.x); Bg[bn + 1][bk] = f2tf(rG.y);
        Bg[bn + 2][bk] = f2tf(rG.z); Bg[bn + 3][bk] = f2tf(rG.w);
        Bu[bn + 0][bk] = f2tf(rU.x); Bu[bn + 1][bk] = f2tf(rU.y);
        Bu[bn + 2][bk] = f2tf(rU.z); Bu[bn + 3][bk] = f2tf(rU.w);
        __syncthreads();

        for (int k0 = 0; k0 < HD; k0 += 16) {
            bool more = (k0 + 16) < HD;
            if (more) {
                int kn = k0 + 16;
#pragma unroll
                for (int p = 0; p < 2; p++) {
                    int s = tid + p * 256, r = s >> 2, kc = (s & 3) * 4;
                    rA[p] = (r < nt) ? *(const float4*)&x[(size_t)toks[r] * HD + kn + kc]
                                     : make_float4(0.f, 0.f, 0.f, 0.f);
                }
                rG = *(const float4*)&wg[(size_t)(kn + bk) * FF + bn];
                rU = *(const float4*)&wu[(size_t)(kn + bk) * FF + bn];
            }
#pragma unroll
            for (int k8 = 0; k8 < 2; k8++) {
                int kb = k8 * 8 + lr;
                unsigned a[2][4];
#pragma unroll
                for (int mi = 0; mi < 2; mi++) {
                    int r = wm * 32 + mi * 16 + lq;
                    a[mi][0] = As[r][kb];     a[mi][1] = As[r + 8][kb];
                    a[mi][2] = As[r][kb + 4]; a[mi][3] = As[r + 8][kb + 4];
                }
#pragma unroll
                for (int ni = 0; ni < 4; ni++) {
                    int nn = wn * 32 + ni * 8 + lq;
                    unsigned g0 = Bg[nn][kb], g1 = Bg[nn][kb + 4];
                    unsigned u0 = Bu[nn][kb], u1 = Bu[nn][kb + 4];
#pragma unroll
                    for (int mi = 0; mi < 2; mi++) {
                        mma_tf32(accg[mi][ni][0], accg[mi][ni][1], accg[mi][ni][2], accg[mi][ni][3],
                                 a[mi][0], a[mi][1], a[mi][2], a[mi][3], g0, g1);
                        mma_tf32(accu[mi][ni][0], accu[mi][ni][1], accu[mi][ni][2], accu[mi][ni][3],
                                 a[mi][0], a[mi][1], a[mi][2], a[mi][3], u0, u1);
                    }
                }
            }
            __syncthreads();
            if (more) {
#pragma unroll
                for (int p = 0; p < 2; p++) {
                    int s = tid + p * 256, r = s >> 2, kc = (s & 3) * 4;
                    uint4 w = {f2tf(rA[p].x), f2tf(rA[p].y), f2tf(rA[p].z), f2tf(rA[p].w)};
                    *(uint4*)&As[r][kc] = w;
                }
                Bg[bn + 0][bk] = f2tf(rG.x); Bg[bn + 1][bk] = f2tf(rG.y);
                Bg[bn + 2][bk] = f2tf(rG.z); Bg[bn + 3][bk] = f2tf(rG.w);
                Bu[bn + 0][bk] = f2tf(rU.x); Bu[bn + 1][bk] = f2tf(rU.y);
                Bu[bn + 2][bk] = f2tf(rU.z); Bu[bn + 3][bk] = f2tf(rU.w);
                __syncthreads();
            }
        }
        // epilogue: SwiGLU * comb -> g_act
#pragma unroll
        for (int mi = 0; mi < 2; mi++)
#pragma unroll
            for (int half = 0; half < 2; half++) {
                int r = wm * 32 + mi * 16 + lq + half * 8;
                if (r < nt) {
                    float wc = g_wgt[e * TT + s0 + r];
                    size_t base = ((size_t)e * TT + s0 + r) * FF + f0 + wn * 32;
#pragma unroll
                    for (int ni = 0; ni < 4; ni++)
#pragma unroll
                        for (int c = 0; c < 2; c++) {
                            float gv = accg[mi][ni][half * 2 + c];
                            float uv = accu[mi][ni][half * 2 + c];
                            float act = gv / (1.0f + expf(-gv)) * uv * wc;
                            g_act[base + ni * 8 + lr * 2 + c] = act;
                        }
                }
            }
    }
}

// ---------------------------------------------------------------------------
// K4: down projection. M=128 gathered tokens, N=64 over H, K=FF. tf32 mma.
// grid (HD/64, EE). atomicAdd into out.
// ---------------------------------------------------------------------------
__global__ __launch_bounds__(256, 2) void k_down(const float* __restrict__ Wd,
                                                 float* __restrict__ out) {
    int e = blockIdx.y;
    int n = g_cnt[e];
    if (n == 0) return;
    int h0 = blockIdx.x * 64;
    __shared__ unsigned As[128][20];
    __shared__ unsigned Bs[64][20];
    __shared__ int toks[128];
    int tid = threadIdx.x, lane = tid & 31, warp = tid >> 5;
    int wm = warp >> 1, wn = warp & 1;
    int lq = lane >> 2, lr = lane & 3;
    const float* wd = Wd + (size_t)e * FF * HD + h0;
    int bk = tid & 15;
    int bn = (tid >> 4) * 4;

    for (int s0 = 0; s0 < n; s0 += 128) {
        __syncthreads();
        int nt = min(128, n - s0);
        if (tid < 128) toks[tid] = (tid < nt) ? g_tok[e * TT + s0 + tid] : 0;
        __syncthreads();

        float acc[2][4][4] = {};
        float4 rA[2], rB;

#pragma unroll
        for (int p = 0; p < 2; p++) {
            int s = tid + p * 256, r = s >> 2, kc = (s & 3) * 4;
            rA[p] = (r < nt) ? *(const float4*)&g_act[((size_t)e * TT + s0 + r) * FF + kc]
                             : make_float4(0.f, 0.f, 0.f, 0.f);
        }
        rB = *(const float4*)&wd[(size_t)bk * HD + bn];
#pragma unroll
        for (int p = 0; p < 2; p++) {
            int s = tid + p * 256, r = s >> 2, kc = (s & 3) * 4;
            uint4 w = {f2tf(rA[p].x), f2tf(rA[p].y), f2tf(rA[p].z), f2tf(rA[p].w)};
            *(uint4*)&As[r][kc] = w;
        }
        Bs[bn + 0][bk] = f2tf(rB.x); Bs[bn + 1][bk] = f2tf(rB.y);
        Bs[bn + 2][bk] = f2tf(rB.z); Bs[bn + 3][bk] = f2tf(rB.w);
        __syncthreads();

        for (int k0 = 0; k0 < FF; k0 += 16) {
            bool more = (k0 + 16) < FF;
            if (more) {
                int kn = k0 + 16;
#pragma unroll
                for (int p = 0; p < 2; p++) {
                    int s = tid + p * 256, r = s >> 2, kc = (s & 3) * 4;
                    rA[p] = (r < nt) ? *(const float4*)&g_act[((size_t)e * TT + s0 + r) * FF + kn + kc]
                                     : make_float4(0.f, 0.f, 0.f, 0.f);
                }
                rB = *(const float4*)&wd[(size_t)(kn + bk) * HD + bn];
            }
#pragma unroll
            for (int k8 = 0; k8 < 2; k8++) {
                int kb = k8 * 8 + lr;
                unsigned a[2][4];
#pragma unroll
                for (int mi = 0; mi < 2; mi++) {
                    int r = wm * 32 + mi * 16 + lq;
                    a[mi][0] = As[r][kb];     a[mi][1] = As[r + 8][kb];
                    a[mi][2] = As[r][kb + 4]; a[mi][3] = As[r + 8][kb + 4];
                }
#pragma unroll
                for (int ni = 0; ni < 4; ni++) {
                    int nn = wn * 32 + ni * 8 + lq;
                    unsigned b0 = Bs[nn][kb], b1r = Bs[nn][kb + 4];
#pragma unroll
                    for (int mi = 0; mi < 2; mi++)
                        mma_tf32(acc[mi][ni][0], acc[mi][ni][1], acc[mi][ni][2], acc[mi][ni][3],
                                 a[mi][0], a[mi][1], a[mi][2], a[mi][3], b0, b1r);
                }
            }
            __syncthreads();
            if (more) {
#pragma unroll
                for (int p = 0; p < 2; p++) {
                    int s = tid + p * 256, r = s >> 2, kc = (s & 3) * 4;
                    uint4 w = {f2tf(rA[p].x), f2tf(rA[p].y), f2tf(rA[p].z), f2tf(rA[p].w)};
                    *(uint4*)&As[r][kc] = w;
                }
                Bs[bn + 0][bk] = f2tf(rB.x); Bs[bn + 1][bk] = f2tf(rB.y);
                Bs[bn + 2][bk] = f2tf(rB.z); Bs[bn + 3][bk] = f2tf(rB.w);
                __syncthreads();
            }
        }
        // epilogue: atomicAdd into out
#pragma unroll
        for (int mi = 0; mi < 2; mi++)
#pragma unroll
            for (int half = 0; half < 2; half++) {
                int r = wm * 32 + mi * 16 + lq + half * 8;
                if (r < nt) {
                    int t = toks[r];
                    size_t base = (size_t)t * HD + h0 + wn * 32;
#pragma unroll
                    for (int ni = 0; ni < 4; ni++)
#pragma unroll
                        for (int c = 0; c < 2; c++)
                            atomicAdd(&out[base + ni * 8 + lr * 2 + c],
                                      acc[mi][ni][half * 2 + c]);
                }
            }
    }
}

// ---------------------------------------------------------------------------
// launch
// ---------------------------------------------------------------------------
extern "C" void kernel_launch(void* const* d_in, const int* in_sizes, int n_in,
                              void* d_out, int out_size) {
    const float* x      = (const float*)d_in[0];
    const float* u      = (const float*)d_in[1];
    const float* gate_w = (const float*)d_in[2];
    const float* z_w1   = (const float*)d_in[3];
    const float* z_b1   = (const float*)d_in[4];
    const float* z_w2   = (const float*)d_in[5];
    const float* z_b2   = (const float*)d_in[6];
    const float* Umat   = (const float*)d_in[7];
    const float* Wg     = (const float*)d_in[8];
    const float* Wu     = (const float*)d_in[9];
    const float* Wd     = (const float*)d_in[10];
    float* out = (float*)d_out;

    k_zero<<<(TT * HD + 255) / 256, 256>>>(out);
    k_zh<<<dim3(ZHD / 64, TT / 128), 256>>>(x, z_w1, z_b1);
    k_router<<<TT, 128>>>(x, u, gate_w, z_w2, z_b2, Umat);
    k_gateup<<<dim3(FF / 64, EE), 256>>>(x, Wg, Wu);
    k_down<<<dim3(HD / 64, EE), 256>>>(Wd, out);
}